// round 17
// baseline (speedup 1.0000x reference)
#include <cuda_runtime.h>
#include <cuda_bf16.h>
#include <cuda_fp16.h>

#define N_NODES 50000
#define N_EDGES 800000
#define D 64
#define NBLK ((N_NODES + 255) / 256)   // 196

// ---------------------------------------------------------------------------
// Static device scratch. g_cnt zero at load; scatter_idx re-zeroes it each
// run (after scanfin has consumed it) -> graph-replay deterministic.
// ---------------------------------------------------------------------------
__device__ int    g_cnt[N_NODES];
__device__ int    g_offs[N_NODES + 1];
__device__ int    g_cursor[N_NODES];
__device__ int    g_sorted[N_EDGES];
__device__ __half g_feat_h[N_NODES * D];       // fp16 feat for gather traffic

// Side stream + events for graph-forked overlap (created at program init).
static cudaStream_t g_side;
static cudaEvent_t  g_evFork, g_evJoin;
namespace {
struct _Init {
    _Init() {
        cudaStreamCreateWithFlags(&g_side, cudaStreamNonBlocking);
        cudaEventCreateWithFlags(&g_evFork, cudaEventDisableTiming);
        cudaEventCreateWithFlags(&g_evJoin, cudaEventDisableTiming);
    }
} _g_init;
}

// ---------------------------------------------------------------------------
// 1) Histogram, 4 edges/thread (int4 loads, 4 independent REDs overlap)
// ---------------------------------------------------------------------------
__global__ __launch_bounds__(256) void hist_kernel(const int4* __restrict__ dst4,
                                                   int* __restrict__ cnt)
{
    int q = blockIdx.x * blockDim.x + threadIdx.x;
    if (q >= N_EDGES / 4) return;
    int4 d = __ldg(dst4 + q);
    atomicAdd(&cnt[d.x], 1);
    atomicAdd(&cnt[d.y], 1);
    atomicAdd(&cnt[d.z], 1);
    atomicAdd(&cnt[d.w], 1);
}

// ---------------------------------------------------------------------------
// 2) Merged scan: each block sums cnt[0..bid*256) for its base (L2-hot),
//    then scans its own 256 counters. scatter_idx re-zeroes cnt afterwards.
// ---------------------------------------------------------------------------
__global__ __launch_bounds__(256) void scanfin_kernel(
    const int* __restrict__ cnt, int* __restrict__ offs,
    int* __restrict__ cursor)
{
    __shared__ int sm[256];
    __shared__ int sbase[8];
    const int t = threadIdx.x;
    const int bid = blockIdx.x;

    const int4* cnt4 = (const int4*)cnt;
    int nq = bid * 64;
    int bv = 0;
    for (int i = t; i < nq; i += 256) {
        int4 v = __ldg(cnt4 + i);
        bv += (v.x + v.y) + (v.z + v.w);
    }
#pragma unroll
    for (int o = 16; o > 0; o >>= 1) bv += __shfl_down_sync(~0u, bv, o);
    if ((t & 31) == 0) sbase[t >> 5] = bv;

    int idx = bid * 256 + t;
    int c = (idx < N_NODES) ? __ldg(cnt + idx) : 0;
    sm[t] = c;
    __syncthreads();

    int base = sbase[0] + sbase[1] + sbase[2] + sbase[3] +
               sbase[4] + sbase[5] + sbase[6] + sbase[7];

    for (int off = 1; off < 256; off <<= 1) {
        int u = (t >= off) ? sm[t - off] : 0;
        __syncthreads();
        sm[t] += u;
        __syncthreads();
    }
    int off = base + sm[t] - c;   // exclusive prefix
    if (idx < N_NODES) {
        offs[idx]   = off;
        cursor[idx] = off;
        if (idx == N_NODES - 1) offs[N_NODES] = off + c;  // = N_EDGES
    }
}

// ---------------------------------------------------------------------------
// 3) Scatter, 4 edges/thread; also re-zeroes cnt for the next replay
// ---------------------------------------------------------------------------
__global__ __launch_bounds__(256) void scatter_idx_kernel(
    const int4* __restrict__ src4, const int4* __restrict__ dst4,
    int* __restrict__ cursor, int* __restrict__ sorted,
    int* __restrict__ cnt)
{
    int q = blockIdx.x * blockDim.x + threadIdx.x;
    if (q < N_NODES) cnt[q] = 0;              // replay reset (reads done)
    if (q >= N_EDGES / 4) return;
    int4 s = __ldg(src4 + q);
    int4 d = __ldg(dst4 + q);
    int p0 = atomicAdd(&cursor[d.x], 1);
    int p1 = atomicAdd(&cursor[d.y], 1);
    int p2 = atomicAdd(&cursor[d.z], 1);
    int p3 = atomicAdd(&cursor[d.w], 1);
    sorted[p0] = s.x;
    sorted[p1] = s.y;
    sorted[p2] = s.z;
    sorted[p3] = s.w;
}

// ---------------------------------------------------------------------------
// 4) Convert feat -> fp16 (one pass, streaming)
// ---------------------------------------------------------------------------
__global__ __launch_bounds__(256) void convert_kernel(
    const float4* __restrict__ feat, uint2* __restrict__ feat_h)
{
    int i = blockIdx.x * blockDim.x + threadIdx.x;
    if (i >= N_NODES * 16) return;
    float4 v = feat[i];
    __half2 h0 = __floats2half2_rn(v.x, v.y);
    __half2 h1 = __floats2half2_rn(v.z, v.w);
    uint2 hp;
    hp.x = *(unsigned int*)&h0;
    hp.y = *(unsigned int*)&h1;
    feat_h[i] = hp;
}

// ---------------------------------------------------------------------------
// tf32 helpers
// ---------------------------------------------------------------------------
__device__ __forceinline__ unsigned f2tf32(float a) {
    unsigned r;
    asm("cvt.rna.tf32.f32 %0, %1;" : "=r"(r) : "f"(a));
    return r;
}
__device__ __forceinline__ void mma_tf32(float* c, unsigned a0, unsigned a1,
                                         unsigned a2, unsigned a3,
                                         unsigned b0, unsigned b1) {
    asm("mma.sync.aligned.m16n8k8.row.col.f32.tf32.tf32.f32 "
        "{%0,%1,%2,%3}, {%4,%5,%6,%7}, {%8,%9}, {%0,%1,%2,%3};"
        : "+f"(c[0]), "+f"(c[1]), "+f"(c[2]), "+f"(c[3])
        : "r"(a0), "r"(a1), "r"(a2), "r"(a3), "r"(b0), "r"(b1));
}

// ---------------------------------------------------------------------------
// 5) FUSED: rst = (1+eps)*feat + gather(feat_h); out = rst @ W^T + b.
//    64 nodes/block, 256 threads (8 warps).
//    Phase A (proven gather body): each warp gathers 2 nodes/pass x 4
//    passes (16 lanes/node, fp16 reads, fp32 acc, fp32 residual), STS
//    into the stride-68 tile.
//    Phase B (proven R16 mma): warp = (rgrp 0..3, jhalf 0..1): 16 rows x
//    32 cols, acc[4][4], single-pass tf32; epilogue adds bias, stores out.
// ---------------------------------------------------------------------------
#define FN 64   // nodes per block

__global__ __launch_bounds__(256) void fused_kernel(
    const float4* __restrict__ feat, const uint2* __restrict__ feat_h,
    const float* __restrict__ Wf, const float* __restrict__ b,
    const float* __restrict__ eps, const int* __restrict__ offs,
    const int* __restrict__ sorted, float* __restrict__ out)
{
    __shared__ float tile[FN * 68];      // rst rows, stride 68 (17.4 KB)
    __shared__ uint2 Bfrag[8 * 8 * 32];  // W hi fragments (16 KB)

    const int tid  = threadIdx.x;
    const int row0 = blockIdx.x * FN;
    const int warp = tid >> 5;
    const int lane = tid & 31;

    // Stage B hi-fragments (R16-proven): 2048 entries, 8/thread
    for (int i = tid; i < 8 * 8 * 32; i += 256) {
        int jt = i >> 8, kt = (i >> 5) & 7, ln = i & 31;
        int gg = ln >> 2, tg2 = ln & 3;
        float f0 = __ldg(Wf + (jt * 8 + gg) * 64 + kt * 8 + tg2);
        float f1 = __ldg(Wf + (jt * 8 + gg) * 64 + kt * 8 + tg2 + 4);
        Bfrag[i] = make_uint2(f2tf32(f0), f2tf32(f1));
    }

    // ---- Phase A: gather rst into smem tile ----
    const float sc  = 1.0f + __ldg(eps);
    const int half = lane >> 4;      // 0/1: node within pair
    const int cl   = lane & 15;      // float4 column
    for (int p = 0; p < 4; p++) {
        int lr = warp * 8 + p * 2 + half;   // local row 0..63
        int gn = row0 + lr;
        float4 a = make_float4(0.f, 0.f, 0.f, 0.f);
        if (gn < N_NODES) {
            int beg = __ldg(offs + gn);
            int end = __ldg(offs + gn + 1);
            int e = beg;
            for (; e + 4 <= end; e += 4) {
                int s0 = __ldg(sorted + e);
                int s1 = __ldg(sorted + e + 1);
                int s2 = __ldg(sorted + e + 2);
                int s3 = __ldg(sorted + e + 3);
                uint2 p0 = feat_h[s0 * 16 + cl];
                uint2 p1 = feat_h[s1 * 16 + cl];
                uint2 p2 = feat_h[s2 * 16 + cl];
                uint2 p3 = feat_h[s3 * 16 + cl];
                float2 f;
                f = __half22float2(*(__half2*)&p0.x); a.x += f.x; a.y += f.y;
                f = __half22float2(*(__half2*)&p0.y); a.z += f.x; a.w += f.y;
                f = __half22float2(*(__half2*)&p1.x); a.x += f.x; a.y += f.y;
                f = __half22float2(*(__half2*)&p1.y); a.z += f.x; a.w += f.y;
                f = __half22float2(*(__half2*)&p2.x); a.x += f.x; a.y += f.y;
                f = __half22float2(*(__half2*)&p2.y); a.z += f.x; a.w += f.y;
                f = __half22float2(*(__half2*)&p3.x); a.x += f.x; a.y += f.y;
                f = __half22float2(*(__half2*)&p3.y); a.z += f.x; a.w += f.y;
            }
            for (; e < end; e++) {
                int s = __ldg(sorted + e);
                uint2 pp = feat_h[s * 16 + cl];
                float2 f;
                f = __half22float2(*(__half2*)&pp.x); a.x += f.x; a.y += f.y;
                f = __half22float2(*(__half2*)&pp.y); a.z += f.x; a.w += f.y;
            }
            float4 yg = feat[gn * 16 + cl];   // residual stays fp32
            a.x += sc * yg.x;
            a.y += sc * yg.y;
            a.z += sc * yg.z;
            a.w += sc * yg.w;
        }
        ((float4*)(tile + lr * 68))[cl] = a;
    }
    __syncthreads();

    // ---- Phase B: tf32 mma (R16-proven fragments) ----
    const int g     = lane >> 2;          // 0..7
    const int tg    = lane & 3;           // 0..3
    const int r0    = (warp & 3) * 16;    // 16-row group
    const int jbase = (warp >> 2) * 4;    // 4 jt tiles (32 cols)

    float acc[4][4];
#pragma unroll
    for (int j = 0; j < 4; j++)
#pragma unroll
        for (int q = 0; q < 4; q++) acc[j][q] = 0.f;

    for (int kt = 0; kt < 8; kt++) {
        unsigned ah0 = f2tf32(tile[(r0 + g) * 68 + kt * 8 + tg]);
        unsigned ah1 = f2tf32(tile[(r0 + g + 8) * 68 + kt * 8 + tg]);
        unsigned ah2 = f2tf32(tile[(r0 + g) * 68 + kt * 8 + tg + 4]);
        unsigned ah3 = f2tf32(tile[(r0 + g + 8) * 68 + kt * 8 + tg + 4]);
#pragma unroll
        for (int j = 0; j < 4; j++) {
            int jt = jbase + j;
            uint2 bb = Bfrag[(jt * 8 + kt) * 32 + lane];
            mma_tf32(acc[j], ah0, ah1, ah2, ah3, bb.x, bb.y);
        }
    }

    // Epilogue: add bias, store out. c0,c1 -> row g; c2,c3 -> row g+8.
#pragma unroll
    for (int j = 0; j < 4; j++) {
        int col = (jbase + j) * 8 + 2 * tg;
        float b0 = __ldg(b + col);
        float b1 = __ldg(b + col + 1);
        int rA = row0 + r0 + g;
        int rB = rA + 8;
        if (rA < N_NODES)
            *(float2*)(out + rA * 64 + col) =
                make_float2(acc[j][0] + b0, acc[j][1] + b1);
        if (rB < N_NODES)
            *(float2*)(out + rB * 64 + col) =
                make_float2(acc[j][2] + b0, acc[j][3] + b1);
    }
}

// ---------------------------------------------------------------------------
// Launch: inputs per metadata order: feat, W, b, eps, src, dst
// Fork: CSR build (side) overlaps feat->fp16 convert (main); join -> fused.
// 5 launches total.
// ---------------------------------------------------------------------------
extern "C" void kernel_launch(void* const* d_in, const int* in_sizes, int n_in,
                              void* d_out, int out_size)
{
    const float4* feat = (const float4*)d_in[0];
    const float*  Wf   = (const float*)d_in[1];
    const float*  b    = (const float*)d_in[2];
    const float*  eps  = (const float*)d_in[3];
    const int4*   src4 = (const int4*)d_in[4];
    const int4*   dst4 = (const int4*)d_in[5];
    float*        out  = (float*)d_out;

    int *cnt, *offs, *cursor, *sorted;
    __half* feat_h;
    cudaGetSymbolAddress((void**)&cnt,    g_cnt);
    cudaGetSymbolAddress((void**)&offs,   g_offs);
    cudaGetSymbolAddress((void**)&cursor, g_cursor);
    cudaGetSymbolAddress((void**)&sorted, g_sorted);
    cudaGetSymbolAddress((void**)&feat_h, g_feat_h);

    const int EQ = (N_EDGES / 4 + 255) / 256;   // 782 blocks, 4 edges/thread

    // Fork: CSR build chain on side stream
    cudaEventRecord(g_evFork, 0);
    cudaStreamWaitEvent(g_side, g_evFork, 0);
    hist_kernel<<<EQ, 256, 0, g_side>>>(dst4, cnt);
    scanfin_kernel<<<NBLK, 256, 0, g_side>>>(cnt, offs, cursor);
    scatter_idx_kernel<<<EQ, 256, 0, g_side>>>(src4, dst4, cursor, sorted, cnt);
    cudaEventRecord(g_evJoin, g_side);

    // Main stream: feat -> fp16 (overlaps the CSR build)
    {
        int n = N_NODES * 16;
        convert_kernel<<<(n + 255) / 256, 256>>>(feat, (uint2*)feat_h);
    }

    // Join, then fused gather+GEMM writes out directly
    cudaStreamWaitEvent(0, g_evJoin, 0);
    {
        int blocks = (N_NODES + FN - 1) / FN;   // 782
        fused_kernel<<<blocks, 256>>>(feat, (const uint2*)feat_h, Wf, b, eps,
                                      offs, sorted, out);
    }
}